// round 15
// baseline (speedup 1.0000x reference)
#include <cuda_runtime.h>
#include <cuda_bf16.h>
#include <stdint.h>
#include <stddef.h>

#define BB 32768
#define MM 8192
#define GG 64
#define NCELL (GG*GG)

static __device__ __forceinline__ float f_inf() { return __int_as_float(0x7f800000); }

// ---------------- scratch (device globals; no allocation allowed) ----------------
__device__ float  g_X1[BB*128];
__device__ float  g_X2[BB*256];
__device__ float  g_X3[BB*512];
__device__ float  g_X4[BB*128];
__device__ float  g_X5[BB*64];
__device__ __nv_bfloat16 g_AH[BB*128];   // L1 input planes (from knn)
__device__ __nv_bfloat16 g_AL[BB*128];
__device__ __nv_bfloat16 g_W1H[128*128], g_W1L[128*128];   // [N][Kpad]
__device__ __nv_bfloat16 g_W2H[256*128], g_W2L[256*128];
__device__ __nv_bfloat16 g_W3H[512*256], g_W3L[512*256];
__device__ __nv_bfloat16 g_W4H[128*512], g_W4L[128*512];
__device__ __nv_bfloat16 g_W5H[64*128],  g_W5L[64*128];
__device__ float  g_psum[256*512];
__device__ float  g_psq [256*512];
__device__ float  g_scale[512];
__device__ float  g_shift[512];
__device__ int    g_cellCount[NCELL];
__device__ int    g_cellFill [NCELL];
__device__ int    g_cellStart[NCELL+1];
__device__ int    g_qCount[NCELL];
__device__ int    g_qFill [NCELL];
__device__ int    g_qStart[NCELL+1];
__device__ int    g_qIdx[BB];
__device__ float4 g_packed[MM];

// ---------------- PTX helpers ----------------
static __device__ __forceinline__ uint32_t smem_u32(const void* p) {
    uint32_t a;
    asm("{ .reg .u64 t; cvta.to.shared.u64 t, %1; cvt.u32.u64 %0, t; }" : "=r"(a) : "l"(p));
    return a;
}
static __device__ __forceinline__ void ldsm4(uint32_t* r, uint32_t a) {
    asm volatile("ldmatrix.sync.aligned.m8n8.x4.shared.b16 {%0,%1,%2,%3}, [%4];"
        : "=r"(r[0]), "=r"(r[1]), "=r"(r[2]), "=r"(r[3]) : "r"(a));
}
static __device__ __forceinline__ void mma16816(float* d, const uint32_t* a,
                                                uint32_t b0, uint32_t b1) {
    asm volatile("mma.sync.aligned.m16n8k16.row.col.f32.bf16.bf16.f32 "
        "{%0,%1,%2,%3}, {%4,%5,%6,%7}, {%8,%9}, {%0,%1,%2,%3};"
        : "+f"(d[0]), "+f"(d[1]), "+f"(d[2]), "+f"(d[3])
        : "r"(a[0]), "r"(a[1]), "r"(a[2]), "r"(a[3]), "r"(b0), "r"(b1));
}
static __device__ __forceinline__ void bsplit(float a, __nv_bfloat16& h, __nv_bfloat16& l) {
    h = __float2bfloat16_rn(a);
    l = __float2bfloat16_rn(a - __bfloat162float(h));
}

// ---------------- grid build ----------------
__global__ void zero_cells_kernel() {
    int i = blockIdx.x*blockDim.x + threadIdx.x;
    if (i < NCELL) { g_cellCount[i] = 0; g_cellFill[i] = 0; g_qCount[i] = 0; g_qFill[i] = 0; }
}

__device__ __forceinline__ int cell_of(float v) {
    const float GMINF = -6.0f;
    const float INVH  = GG / 12.0f;
    int c = (int)floorf((v - GMINF) * INVH);
    return min(max(c, 0), GG-1);
}

// merged measure + query cell counting
__global__ void count2_kernel(const float* __restrict__ mc, const float* __restrict__ pos) {
    int i = blockIdx.x*blockDim.x + threadIdx.x;
    if (i < MM) {
        atomicAdd(&g_cellCount[cell_of(mc[2*i+1])*GG + cell_of(mc[2*i])], 1);
    } else if (i < MM + BB) {
        int j = i - MM;
        atomicAdd(&g_qCount[cell_of(pos[2*j+1])*GG + cell_of(pos[2*j])], 1);
    }
}

// block 0: measure-cell scan; block 1: query-cell scan
__global__ void scan2_kernel() {
    __shared__ int sums[256];
    const int* cnt = (blockIdx.x == 0) ? g_cellCount : g_qCount;
    int* start     = (blockIdx.x == 0) ? g_cellStart : g_qStart;
    int t = threadIdx.x;
    const int per = NCELL / 256;
    int base = t * per;
    int s = 0;
    for (int i = 0; i < per; i++) s += cnt[base + i];
    sums[t] = s;
    __syncthreads();
    if (t == 0) {
        int acc = 0;
        for (int i = 0; i < 256; i++) { int v = sums[i]; sums[i] = acc; acc += v; }
    }
    __syncthreads();
    int off = sums[t];
    for (int i = 0; i < per; i++) { int v = cnt[base + i]; start[base + i] = off; off += v; }
    if (t == 255) start[NCELL] = off;
}

// merged measure + query scatter
__global__ void scatter2_kernel(const float* __restrict__ mc, const float* __restrict__ pos) {
    int i = blockIdx.x*blockDim.x + threadIdx.x;
    if (i < MM) {
        float x = mc[2*i], y = mc[2*i+1];
        int c = cell_of(y)*GG + cell_of(x);
        int slot = g_cellStart[c] + atomicAdd(&g_cellFill[c], 1);
        float sm = __fadd_rn(__fmul_rn(x, x), __fmul_rn(y, y));
        g_packed[slot] = make_float4(x, y, sm, __int_as_float(i));
    } else if (i < MM + BB) {
        int j = i - MM;
        int c = cell_of(pos[2*j+1])*GG + cell_of(pos[2*j]);
        int slot = g_qStart[c] + atomicAdd(&g_qFill[c], 1);
        g_qIdx[slot] = j;
    }
}

// all 5 weight transposes + splits in one kernel
__global__ void wtconv_all_kernel(
    const float* __restrict__ w1, const float* __restrict__ w2,
    const float* __restrict__ w3, const float* __restrict__ w4,
    const float* __restrict__ w5)
{
    int idx = blockIdx.x*blockDim.x + threadIdx.x;
    const float* w; __nv_bfloat16 *WH, *WL; int K, N, Kpad, loc;
    if (idx < 16384)       { w=w1; WH=g_W1H; WL=g_W1L; K=66;  N=128; Kpad=128; loc=idx; }
    else if (idx < 49152)  { w=w2; WH=g_W2H; WL=g_W2L; K=128; N=256; Kpad=128; loc=idx-16384; }
    else if (idx < 180224) { w=w3; WH=g_W3H; WL=g_W3L; K=256; N=512; Kpad=256; loc=idx-49152; }
    else if (idx < 245760) { w=w4; WH=g_W4H; WL=g_W4L; K=512; N=128; Kpad=512; loc=idx-180224; }
    else if (idx < 253952) { w=w5; WH=g_W5H; WL=g_W5L; K=128; N=64;  Kpad=128; loc=idx-245760; }
    else return;
    int n = loc / Kpad, k = loc % Kpad;
    float v = (k < K) ? w[(size_t)k * N + n] : 0.0f;
    __nv_bfloat16 h, l;
    bsplit(v, h, l);
    WH[loc] = h;
    WL[loc] = l;
}

// ---------------- KNN (cell-sorted, plain rings — proven R11 version) ----------
#define SCAN_RANGE(S_, E_)                                                        \
    for (int j_ = (S_); j_ < (E_); j_++) {                                        \
        float4 v_ = g_packed[j_];                                                 \
        float dot_ = __fmaf_rn(py, v_.y, __fmul_rn(px, v_.x));                    \
        float d2_  = __fmaf_rn(dot_, -2.0f, __fadd_rn(sp, v_.z));                 \
        int   mi_  = __float_as_int(v_.w);                                        \
        if (d2_ < key[15] || (d2_ == key[15] && mi_ < id[15])) {                  \
            float ck_ = d2_; int ci_ = mi_;                                       \
            _Pragma("unroll")                                                     \
            for (int t2_ = 0; t2_ < 16; t2_++) {                                  \
                bool sw_ = (ck_ < key[t2_]) || (ck_ == key[t2_] && ci_ < id[t2_]);\
                float tk_ = key[t2_]; int ti_ = id[t2_];                          \
                if (sw_) { key[t2_] = ck_; id[t2_] = ci_; ck_ = tk_; ci_ = ti_; } \
            }                                                                     \
        }                                                                         \
    }

__global__ void __launch_bounds__(256) knn_kernel(
    const float* __restrict__ pos, const float* __restrict__ mc,
    const float* __restrict__ mv, float* __restrict__ outKnn)
{
    const float GMINF = -6.0f;
    const float HCELL = 12.0f / GG;
    const float MARGIN = 1e-4f;
    int slot = blockIdx.x*blockDim.x + threadIdx.x;
    if (slot >= BB) return;
    int q = g_qIdx[slot];
    float px = pos[2*q], py = pos[2*q+1];
    float sp = __fadd_rn(__fmul_rn(px, px), __fmul_rn(py, py));

    float key[16]; int id[16];
#pragma unroll
    for (int i = 0; i < 16; i++) { key[i] = f_inf(); id[i] = 0x7fffffff; }

    int cx = cell_of(px), cy = cell_of(py);

    for (int R = 0;; R++) {
        int xlo = cx - R, xhi = cx + R, ylo = cy - R, yhi = cy + R;
        int xl = max(xlo, 0), xh = min(xhi, GG-1);
        int yl = max(ylo, 0), yh = min(yhi, GG-1);
        for (int yy = yl; yy <= yh; yy++) {
            if (yy == ylo || yy == yhi) {
                int s = g_cellStart[yy*GG + xl];
                int e = g_cellStart[yy*GG + xh + 1];
                SCAN_RANGE(s, e)
            } else {
                if (xlo >= 0) {
                    int s = g_cellStart[yy*GG + xlo];
                    int e = g_cellStart[yy*GG + xlo + 1];
                    SCAN_RANGE(s, e)
                }
                if (xhi <= GG-1) {
                    int s = g_cellStart[yy*GG + xhi];
                    int e = g_cellStart[yy*GG + xhi + 1];
                    SCAN_RANGE(s, e)
                }
            }
        }
        bool full = (xlo <= 0 && ylo <= 0 && xhi >= GG-1 && yhi >= GG-1);
        float x0 = GMINF + xlo * HCELL, x1 = GMINF + (xhi + 1) * HCELL;
        float y0 = GMINF + ylo * HCELL, y1 = GMINF + (yhi + 1) * HCELL;
        float db = fminf(fminf(px - x0, x1 - px), fminf(py - y0, y1 - py));
        if (full || (db > 0.0f && db*db > key[15] + MARGIN)) break;
    }

    float* o = outKnn + (size_t)q * 66;
    __nv_bfloat16* xh = g_AH + (size_t)q * 128;
    __nv_bfloat16* xl = g_AL + (size_t)q * 128;
    float feat[66];
    feat[0] = px; feat[1] = py;
#pragma unroll
    for (int n = 0; n < 16; n++) {
        int mi = id[n];
        feat[2+4*n] = mc[2*mi];
        feat[3+4*n] = mc[2*mi+1];
        feat[4+4*n] = mv[2*mi];
        feat[5+4*n] = mv[2*mi+1];
    }
#pragma unroll
    for (int c = 0; c < 66; c++) {
        o[c] = feat[c];
        __nv_bfloat16 h, l;
        bsplit(feat[c], h, l);
        xh[c] = h; xl[c] = l;
    }
#pragma unroll
    for (int c = 66; c < 128; c++) { xh[c] = __float2bfloat16(0.0f); xl[c] = __float2bfloat16(0.0f); }
}

// ---------------- HMMA bf16x3 GEMM (2 CTA/SM), fused BN+ReLU+split in A-fill --
// BNIN=true : A is fp32 X[B][lda]; BN(scale,shift)+ReLU+bsplit applied in fill.
// BNIN=false: A given as pre-split planes APH/APL [B][lda].
template<int BNT, bool BNIN>
__global__ void __launch_bounds__(256, 2)
gemm5_kernel(const float* __restrict__ Afp,
             const __nv_bfloat16* __restrict__ APH, const __nv_bfloat16* __restrict__ APL,
             int lda,
             const __nv_bfloat16* __restrict__ WH, const __nv_bfloat16* __restrict__ WL,
             const float* __restrict__ bias, float* __restrict__ C,
             int K, int N)
{
    extern __shared__ char sm[];
    constexpr int NW  = BNT / 2;
    constexpr int NB8 = NW / 8;
    constexpr int NG  = NW / 16;
    constexpr int SS  = BNT + 4;
    constexpr int TIL = 2560;
    constexpr int AHI = TIL;
    constexpr int ALO = AHI + 128*144;
    constexpr int BHI = ALO + 128*144;
    constexpr int BLO = BHI + BNT*144;
    constexpr int TEND = BLO + BNT*144;
    constexpr int STGO = TIL;                // aliases tiles in epilogue
    constexpr int RED  = TEND;
    constexpr int SCo  = TEND + 2048;        // scale/shift (512 floats each)

    uint32_t sbase = smem_u32(sm);
    int tid = threadIdx.x;
    int wid = tid >> 5, lane = tid & 31;
    int wm = wid & 3, wn = wid >> 2;
    int row0 = blockIdx.y * 128;
    int col0 = blockIdx.x * BNT;

    float* sBias = (float*)(sm + 0);
    float* sSc   = (float*)(sm + SCo);
    float* sSh   = (float*)(sm + SCo + 2048);
    for (int i = tid; i < BNT; i += 256) sBias[i] = bias[col0 + i];
    if (BNIN) {
        for (int i = tid; i < K; i += 256) { sSc[i] = g_scale[i]; sSh[i] = g_shift[i]; }
    }
    __syncthreads();

    float d[2][NB8][4];
#pragma unroll
    for (int mt = 0; mt < 2; mt++)
#pragma unroll
        for (int nb = 0; nb < NB8; nb++)
#pragma unroll
            for (int j = 0; j < 4; j++) d[mt][nb][j] = 0.0f;

    const int nst = K / 64;
    for (int s = 0; s < nst; s++) {
        int k0 = s * 64;
        // --- A tile: 128 rows x 64 k ---
#pragma unroll
        for (int it = 0; it < 8; it++) {
            int idx = tid + it * 256;
            int m = idx >> 4;
            int kc = (idx & 15) * 4;
            if (BNIN) {
                float4 a = *(const float4*)(Afp + (size_t)(row0 + m) * lda + k0 + kc);
                float av[4] = {a.x, a.y, a.z, a.w};
#pragma unroll
                for (int j = 0; j < 4; j++)
                    av[j] = fmaxf(0.0f, fmaf(av[j], sSc[k0+kc+j], sSh[k0+kc+j]));
                __nv_bfloat16 h[4], l[4];
#pragma unroll
                for (int j = 0; j < 4; j++) bsplit(av[j], h[j], l[j]);
                __nv_bfloat162 h0 = __halves2bfloat162(h[0], h[1]);
                __nv_bfloat162 h1 = __halves2bfloat162(h[2], h[3]);
                __nv_bfloat162 l0 = __halves2bfloat162(l[0], l[1]);
                __nv_bfloat162 l1 = __halves2bfloat162(l[2], l[3]);
                uint2 uh; uh.x = *(uint32_t*)&h0; uh.y = *(uint32_t*)&h1;
                uint2 ul; ul.x = *(uint32_t*)&l0; ul.y = *(uint32_t*)&l1;
                *(uint2*)(sm + AHI + m*144 + kc*2) = uh;
                *(uint2*)(sm + ALO + m*144 + kc*2) = ul;
            } else {
                size_t go = (size_t)(row0 + m) * lda + k0 + kc;
                *(uint2*)(sm + AHI + m*144 + kc*2) = *(const uint2*)(APH + go);
                *(uint2*)(sm + ALO + m*144 + kc*2) = *(const uint2*)(APL + go);
            }
        }
        // --- B planes: BNT rows x 64 k ---
#pragma unroll
        for (int it = 0; it < BNT/16; it++) {
            int idx = tid + it * 256;
            int n = idx >> 4;
            int kc = (idx & 15) * 4;
            size_t go = (size_t)(col0 + n) * K + k0 + kc;
            *(uint2*)(sm + BHI + n*144 + kc*2) = *(const uint2*)(WH + go);
            *(uint2*)(sm + BLO + n*144 + kc*2) = *(const uint2*)(WL + go);
        }
        __syncthreads();

        int lr = lane & 15, lc = lane >> 4;
#pragma unroll
        for (int kst = 0; kst < 4; kst++) {
            uint32_t koff = (uint32_t)(kst * 16 + lc * 8) * 2;
            uint32_t bh[NG][4], bl[NG][4];
#pragma unroll
            for (int g = 0; g < NG; g++) {
                uint32_t bo = (uint32_t)((wn*NW + g*16 + lr) * 72) * 2 + koff;
                ldsm4(bh[g], sbase + BHI + bo);
                ldsm4(bl[g], sbase + BLO + bo);
            }
#pragma unroll
            for (int mt = 0; mt < 2; mt++) {
                uint32_t ao = (uint32_t)((wm*32 + mt*16 + lr) * 72) * 2 + koff;
                uint32_t ah[4], al[4];
                ldsm4(ah, sbase + AHI + ao);
                ldsm4(al, sbase + ALO + ao);
#pragma unroll
                for (int g = 0; g < NG; g++) {
                    mma16816(d[mt][2*g],   ah, bh[g][0], bh[g][2]);
                    mma16816(d[mt][2*g],   ah, bl[g][0], bl[g][2]);
                    mma16816(d[mt][2*g],   al, bh[g][0], bh[g][2]);
                    mma16816(d[mt][2*g+1], ah, bh[g][1], bh[g][3]);
                    mma16816(d[mt][2*g+1], ah, bl[g][1], bl[g][3]);
                    mma16816(d[mt][2*g+1], al, bh[g][1], bh[g][3]);
                }
            }
        }
        __syncthreads();
    }

    float* stg = (float*)(sm + STGO);
    float* red = (float*)(sm + RED);
#pragma unroll
    for (int mt = 0; mt < 2; mt++)
#pragma unroll
        for (int nb = 0; nb < NB8; nb++) {
            int col = wn*NW + nb*8 + 2*(lane & 3);
            int row = wm*32 + mt*16 + (lane >> 2);
            float b0 = sBias[col], b1 = sBias[col+1];
            stg[row*SS + col]       = d[mt][nb][0] + b0;
            stg[row*SS + col + 1]   = d[mt][nb][1] + b1;
            stg[(row+8)*SS + col]   = d[mt][nb][2] + b0;
            stg[(row+8)*SS + col+1] = d[mt][nb][3] + b1;
        }
    __syncthreads();

    for (int idx = tid; idx < 128 * (BNT/4); idx += 256) {
        int m  = idx / (BNT/4);
        int j4 = (idx % (BNT/4)) * 4;
        float4 v;
        v.x = stg[m*SS + j4 + 0];
        v.y = stg[m*SS + j4 + 1];
        v.z = stg[m*SS + j4 + 2];
        v.w = stg[m*SS + j4 + 3];
        *(float4*)(C + (size_t)(row0 + m) * N + col0 + j4) = v;
    }

#pragma unroll
    for (int c = 0; c < BNT/32; c++) {
        int j = tid & 31, seg = tid >> 5;
        float s2 = 0.0f, q2 = 0.0f;
        for (int r2 = 0; r2 < 16; r2++) {
            float v = stg[(seg*16 + r2) * SS + c*32 + j];
            s2 += v;
            q2 = fmaf(v, v, q2);
        }
        red[seg*32 + j] = s2;
        red[256 + seg*32 + j] = q2;
        __syncthreads();
        if (tid < 32) {
            float s = 0.0f, q = 0.0f;
            for (int u = 0; u < 8; u++) { s += red[u*32 + tid]; q += red[256 + u*32 + tid]; }
            g_psum[blockIdx.y * N + col0 + c*32 + tid] = s;
            g_psq [blockIdx.y * N + col0 + c*32 + tid] = q;
        }
        __syncthreads();
    }
}

// ---------------- BN finalize ----------------
__global__ void bnfin_kernel(const float* __restrict__ g, const float* __restrict__ be, int N) {
    int c = blockIdx.x * 64 + threadIdx.x;
    if (c >= N) return;
    double s = 0.0, q = 0.0;
    for (int rb = 0; rb < 256; rb++) { s += (double)g_psum[rb * N + c]; q += (double)g_psq[rb * N + c]; }
    double mean = s / (double)BB;
    double var  = q / (double)BB - mean * mean;
    float sc = g[c] * rsqrtf((float)var + 1e-5f);
    g_scale[c] = sc;
    g_shift[c] = be[c] - (float)mean * sc;
}

// ---------------- final layer 64 -> 2 (with fused BN5+ReLU) ----------------
__global__ void __launch_bounds__(256) layer6_kernel(
    const float* __restrict__ w6, const float* __restrict__ b6, float* __restrict__ out)
{
    __shared__ float w[128];
    __shared__ float sc[64], sh[64];
    __shared__ float bb2[2];
    int t = threadIdx.x;
    if (t < 128) w[t] = w6[t];
    if (t < 64) { sc[t] = g_scale[t]; sh[t] = g_shift[t]; }
    if (t < 2) bb2[t] = b6[t];
    __syncthreads();
    int r = blockIdx.x * blockDim.x + t;
    if (r >= BB) return;
    const float* x = g_X5 + (size_t)r * 64;
    float a0 = bb2[0], a1 = bb2[1];
#pragma unroll
    for (int k = 0; k < 64; k++) {
        float v = fmaxf(0.0f, fmaf(x[k], sc[k], sh[k]));
        a0 = fmaf(v, w[2*k],   a0);
        a1 = fmaf(v, w[2*k+1], a1);
    }
    out[2*r]   = a0;
    out[2*r+1] = a1;
}

// ---------------- launch ----------------
extern "C" void kernel_launch(void* const* d_in, const int* in_sizes, int n_in,
                              void* d_out, int out_size) {
    const float* pos = (const float*)d_in[0];
    const float* mc  = (const float*)d_in[1];
    const float* mv  = (const float*)d_in[2];
    const float* w1 = (const float*)d_in[3];  const float* b1 = (const float*)d_in[4];
    const float* w2 = (const float*)d_in[5];  const float* b2 = (const float*)d_in[6];
    const float* w3 = (const float*)d_in[7];  const float* b3 = (const float*)d_in[8];
    const float* w4 = (const float*)d_in[9];  const float* b4 = (const float*)d_in[10];
    const float* w5 = (const float*)d_in[11]; const float* b5 = (const float*)d_in[12];
    const float* w6 = (const float*)d_in[13]; const float* b6 = (const float*)d_in[14];
    const float* g1 = (const float*)d_in[15]; const float* be1 = (const float*)d_in[16];
    const float* g2 = (const float*)d_in[17]; const float* be2 = (const float*)d_in[18];
    const float* g3 = (const float*)d_in[19]; const float* be3 = (const float*)d_in[20];
    const float* g4 = (const float*)d_in[21]; const float* be4 = (const float*)d_in[22];
    const float* g5 = (const float*)d_in[23]; const float* be5 = (const float*)d_in[24];
    float* out = (float*)d_out;

    float *X1, *X2, *X3, *X4, *X5;
    cudaGetSymbolAddress((void**)&X1,  g_X1);
    cudaGetSymbolAddress((void**)&X2,  g_X2);
    cudaGetSymbolAddress((void**)&X3,  g_X3);
    cudaGetSymbolAddress((void**)&X4,  g_X4);
    cudaGetSymbolAddress((void**)&X5,  g_X5);
    __nv_bfloat16 *AH, *AL, *W1H, *W1L, *W2H, *W2L, *W3H, *W3L, *W4H, *W4L, *W5H, *W5L;
    cudaGetSymbolAddress((void**)&AH,  g_AH);
    cudaGetSymbolAddress((void**)&AL,  g_AL);
    cudaGetSymbolAddress((void**)&W1H, g_W1H); cudaGetSymbolAddress((void**)&W1L, g_W1L);
    cudaGetSymbolAddress((void**)&W2H, g_W2H); cudaGetSymbolAddress((void**)&W2L, g_W2L);
    cudaGetSymbolAddress((void**)&W3H, g_W3H); cudaGetSymbolAddress((void**)&W3L, g_W3L);
    cudaGetSymbolAddress((void**)&W4H, g_W4H); cudaGetSymbolAddress((void**)&W4L, g_W4L);
    cudaGetSymbolAddress((void**)&W5H, g_W5H); cudaGetSymbolAddress((void**)&W5L, g_W5L);

    const int SMEM128 = 2560 + 2*128*144 + 2*128*144 + 2048 + 4096;  // 82432
    const int SMEM64  = 2560 + 2*128*144 + 2*64*144  + 2048 + 4096;  // 64000
    cudaFuncSetAttribute(gemm5_kernel<128,false>,
                         cudaFuncAttributeMaxDynamicSharedMemorySize, SMEM128);
    cudaFuncSetAttribute(gemm5_kernel<128,true>,
                         cudaFuncAttributeMaxDynamicSharedMemorySize, SMEM128);
    cudaFuncSetAttribute(gemm5_kernel<64,true>,
                         cudaFuncAttributeMaxDynamicSharedMemorySize, SMEM64);

    // grid build + query sort (5 kernels)
    zero_cells_kernel<<<(NCELL + 255) / 256, 256>>>();
    count2_kernel<<<(MM + BB + 255) / 256, 256>>>(mc, pos);
    scan2_kernel<<<2, 256>>>();
    scatter2_kernel<<<(MM + BB + 255) / 256, 256>>>(mc, pos);
    wtconv_all_kernel<<<(253952 + 255) / 256, 256>>>(w1, w2, w3, w4, w5);

    knn_kernel<<<BB / 256, 256>>>(pos, mc, mv, out + (size_t)BB * 2);

    // L1: planes (from knn) -> X1
    gemm5_kernel<128,false><<<dim3(1, BB/128), 256, SMEM128>>>(
        nullptr, AH, AL, 128, W1H, W1L, b1, X1, 128, 128);
    bnfin_kernel<<<2, 64>>>(g1, be1, 128);

    // L2: fp32 X1 + BN1 fused -> X2
    gemm5_kernel<128,true><<<dim3(2, BB/128), 256, SMEM128>>>(
        X1, nullptr, nullptr, 128, W2H, W2L, b2, X2, 128, 256);
    bnfin_kernel<<<4, 64>>>(g2, be2, 256);

    // L3: fp32 X2 + BN2 fused -> X3
    gemm5_kernel<128,true><<<dim3(4, BB/128), 256, SMEM128>>>(
        X2, nullptr, nullptr, 256, W3H, W3L, b3, X3, 256, 512);
    bnfin_kernel<<<8, 64>>>(g3, be3, 512);

    // L4: fp32 X3 + BN3 fused -> X4
    gemm5_kernel<128,true><<<dim3(1, BB/128), 256, SMEM128>>>(
        X3, nullptr, nullptr, 512, W4H, W4L, b4, X4, 512, 128);
    bnfin_kernel<<<2, 64>>>(g4, be4, 128);

    // L5: fp32 X4 + BN4 fused -> X5
    gemm5_kernel<64,true><<<dim3(1, BB/128), 256, SMEM64>>>(
        X4, nullptr, nullptr, 128, W5H, W5L, b5, X5, 128, 64);
    bnfin_kernel<<<1, 64>>>(g5, be5, 64);

    // L6: 64 -> 2 (BN5+ReLU fused)
    layer6_kernel<<<BB / 256, 256>>>(w6, b6, out);
}

// round 16
// speedup vs baseline: 1.4689x; 1.4689x over previous
#include <cuda_runtime.h>
#include <cuda_bf16.h>
#include <stdint.h>
#include <stddef.h>

#define BB 32768
#define MM 8192
#define GG 64
#define NCELL (GG*GG)

static __device__ __forceinline__ float f_inf() { return __int_as_float(0x7f800000); }

// ---------------- scratch (device globals; no allocation allowed) ----------------
__device__ float  g_X1[BB*128];
__device__ float  g_X2[BB*256];
__device__ float  g_X3[BB*512];
__device__ float  g_X4[BB*128];
__device__ float  g_X5[BB*64];
__device__ __nv_bfloat16 g_AH[BB*512];
__device__ __nv_bfloat16 g_AL[BB*512];
__device__ __nv_bfloat16 g_W1H[128*128], g_W1L[128*128];   // [N][Kpad]
__device__ __nv_bfloat16 g_W2H[256*128], g_W2L[256*128];
__device__ __nv_bfloat16 g_W3H[512*256], g_W3L[512*256];
__device__ __nv_bfloat16 g_W4H[128*512], g_W4L[128*512];
__device__ __nv_bfloat16 g_W5H[64*128],  g_W5L[64*128];
__device__ float  g_psum[256*512];
__device__ float  g_psq [256*512];
__device__ float  g_scale[512];
__device__ float  g_shift[512];
__device__ int    g_cellCount[NCELL];
__device__ int    g_cellFill [NCELL];
__device__ int    g_cellStart[NCELL+1];
__device__ int    g_qCount[NCELL];
__device__ int    g_qFill [NCELL];
__device__ int    g_qStart[NCELL+1];
__device__ int    g_qIdx[BB];
__device__ float4 g_packed[MM];

// ---------------- PTX helpers ----------------
static __device__ __forceinline__ uint32_t smem_u32(const void* p) {
    uint32_t a;
    asm("{ .reg .u64 t; cvta.to.shared.u64 t, %1; cvt.u32.u64 %0, t; }" : "=r"(a) : "l"(p));
    return a;
}
static __device__ __forceinline__ void ldsm4(uint32_t* r, uint32_t a) {
    asm volatile("ldmatrix.sync.aligned.m8n8.x4.shared.b16 {%0,%1,%2,%3}, [%4];"
        : "=r"(r[0]), "=r"(r[1]), "=r"(r[2]), "=r"(r[3]) : "r"(a));
}
static __device__ __forceinline__ void mma16816(float* d, const uint32_t* a,
                                                uint32_t b0, uint32_t b1) {
    asm volatile("mma.sync.aligned.m16n8k16.row.col.f32.bf16.bf16.f32 "
        "{%0,%1,%2,%3}, {%4,%5,%6,%7}, {%8,%9}, {%0,%1,%2,%3};"
        : "+f"(d[0]), "+f"(d[1]), "+f"(d[2]), "+f"(d[3])
        : "r"(a[0]), "r"(a[1]), "r"(a[2]), "r"(a[3]), "r"(b0), "r"(b1));
}
static __device__ __forceinline__ void bsplit(float a, __nv_bfloat16& h, __nv_bfloat16& l) {
    h = __float2bfloat16_rn(a);
    l = __float2bfloat16_rn(a - __bfloat162float(h));
}

// ---------------- grid build ----------------
__global__ void zero_cells_kernel() {
    int i = blockIdx.x*blockDim.x + threadIdx.x;
    if (i < NCELL) { g_cellCount[i] = 0; g_cellFill[i] = 0; g_qCount[i] = 0; g_qFill[i] = 0; }
}

__device__ __forceinline__ int cell_of(float v) {
    const float GMINF = -6.0f;
    const float INVH  = GG / 12.0f;
    int c = (int)floorf((v - GMINF) * INVH);
    return min(max(c, 0), GG-1);
}

// merged measure + query cell counting
__global__ void count2_kernel(const float* __restrict__ mc, const float* __restrict__ pos) {
    int i = blockIdx.x*blockDim.x + threadIdx.x;
    if (i < MM) {
        atomicAdd(&g_cellCount[cell_of(mc[2*i+1])*GG + cell_of(mc[2*i])], 1);
    } else if (i < MM + BB) {
        int j = i - MM;
        atomicAdd(&g_qCount[cell_of(pos[2*j+1])*GG + cell_of(pos[2*j])], 1);
    }
}

// block 0: measure-cell scan; block 1: query-cell scan
__global__ void scan2_kernel() {
    __shared__ int sums[256];
    const int* cnt = (blockIdx.x == 0) ? g_cellCount : g_qCount;
    int* start     = (blockIdx.x == 0) ? g_cellStart : g_qStart;
    int t = threadIdx.x;
    const int per = NCELL / 256;
    int base = t * per;
    int s = 0;
    for (int i = 0; i < per; i++) s += cnt[base + i];
    sums[t] = s;
    __syncthreads();
    if (t == 0) {
        int acc = 0;
        for (int i = 0; i < 256; i++) { int v = sums[i]; sums[i] = acc; acc += v; }
    }
    __syncthreads();
    int off = sums[t];
    for (int i = 0; i < per; i++) { int v = cnt[base + i]; start[base + i] = off; off += v; }
    if (t == 255) start[NCELL] = off;
}

// merged measure + query scatter
__global__ void scatter2_kernel(const float* __restrict__ mc, const float* __restrict__ pos) {
    int i = blockIdx.x*blockDim.x + threadIdx.x;
    if (i < MM) {
        float x = mc[2*i], y = mc[2*i+1];
        int c = cell_of(y)*GG + cell_of(x);
        int slot = g_cellStart[c] + atomicAdd(&g_cellFill[c], 1);
        float sm = __fadd_rn(__fmul_rn(x, x), __fmul_rn(y, y));
        g_packed[slot] = make_float4(x, y, sm, __int_as_float(i));
    } else if (i < MM + BB) {
        int j = i - MM;
        int c = cell_of(pos[2*j+1])*GG + cell_of(pos[2*j]);
        int slot = g_qStart[c] + atomicAdd(&g_qFill[c], 1);
        g_qIdx[slot] = j;
    }
}

// all 5 weight transposes + splits in one kernel
__global__ void wtconv_all_kernel(
    const float* __restrict__ w1, const float* __restrict__ w2,
    const float* __restrict__ w3, const float* __restrict__ w4,
    const float* __restrict__ w5)
{
    int idx = blockIdx.x*blockDim.x + threadIdx.x;
    const float* w; __nv_bfloat16 *WH, *WL; int K, N, Kpad, loc;
    if (idx < 16384)       { w=w1; WH=g_W1H; WL=g_W1L; K=66;  N=128; Kpad=128; loc=idx; }
    else if (idx < 49152)  { w=w2; WH=g_W2H; WL=g_W2L; K=128; N=256; Kpad=128; loc=idx-16384; }
    else if (idx < 180224) { w=w3; WH=g_W3H; WL=g_W3L; K=256; N=512; Kpad=256; loc=idx-49152; }
    else if (idx < 245760) { w=w4; WH=g_W4H; WL=g_W4L; K=512; N=128; Kpad=512; loc=idx-180224; }
    else if (idx < 253952) { w=w5; WH=g_W5H; WL=g_W5L; K=128; N=64;  Kpad=128; loc=idx-245760; }
    else return;
    int n = loc / Kpad, k = loc % Kpad;
    float v = (k < K) ? w[(size_t)k * N + n] : 0.0f;
    __nv_bfloat16 h, l;
    bsplit(v, h, l);
    WH[loc] = h;
    WL[loc] = l;
}

// BN+ReLU + bf16-split of activations: X[B][N] fp32 -> AH/AL [B][N] bf16
__global__ void convbn_kernel(const float* __restrict__ X,
                              __nv_bfloat16* __restrict__ AH, __nv_bfloat16* __restrict__ AL,
                              int N) {
    int i = blockIdx.x*blockDim.x + threadIdx.x;
    int base = i * 4;
    if (base >= BB * N) return;
    int c = base % N;
    float4 x = *(const float4*)(X + base);
    float y[4];
    y[0] = fmaxf(0.0f, fmaf(x.x, g_scale[c+0], g_shift[c+0]));
    y[1] = fmaxf(0.0f, fmaf(x.y, g_scale[c+1], g_shift[c+1]));
    y[2] = fmaxf(0.0f, fmaf(x.z, g_scale[c+2], g_shift[c+2]));
    y[3] = fmaxf(0.0f, fmaf(x.w, g_scale[c+3], g_shift[c+3]));
    __nv_bfloat16 h[4], l[4];
#pragma unroll
    for (int j = 0; j < 4; j++) bsplit(y[j], h[j], l[j]);
    *(__nv_bfloat162*)(AH + base)     = __halves2bfloat162(h[0], h[1]);
    *(__nv_bfloat162*)(AH + base + 2) = __halves2bfloat162(h[2], h[3]);
    *(__nv_bfloat162*)(AL + base)     = __halves2bfloat162(l[0], l[1]);
    *(__nv_bfloat162*)(AL + base + 2) = __halves2bfloat162(l[2], l[3]);
}

// ---------------- KNN (cell-sorted, plain rings — proven R11 version) ----------
#define SCAN_RANGE(S_, E_)                                                        \
    for (int j_ = (S_); j_ < (E_); j_++) {                                        \
        float4 v_ = g_packed[j_];                                                 \
        float dot_ = __fmaf_rn(py, v_.y, __fmul_rn(px, v_.x));                    \
        float d2_  = __fmaf_rn(dot_, -2.0f, __fadd_rn(sp, v_.z));                 \
        int   mi_  = __float_as_int(v_.w);                                        \
        if (d2_ < key[15] || (d2_ == key[15] && mi_ < id[15])) {                  \
            float ck_ = d2_; int ci_ = mi_;                                       \
            _Pragma("unroll")                                                     \
            for (int t2_ = 0; t2_ < 16; t2_++) {                                  \
                bool sw_ = (ck_ < key[t2_]) || (ck_ == key[t2_] && ci_ < id[t2_]);\
                float tk_ = key[t2_]; int ti_ = id[t2_];                          \
                if (sw_) { key[t2_] = ck_; id[t2_] = ci_; ck_ = tk_; ci_ = ti_; } \
            }                                                                     \
        }                                                                         \
    }

__global__ void __launch_bounds__(256) knn_kernel(
    const float* __restrict__ pos, const float* __restrict__ mc,
    const float* __restrict__ mv, float* __restrict__ outKnn)
{
    const float GMINF = -6.0f;
    const float HCELL = 12.0f / GG;
    const float MARGIN = 1e-4f;
    int slot = blockIdx.x*blockDim.x + threadIdx.x;
    if (slot >= BB) return;
    int q = g_qIdx[slot];
    float px = pos[2*q], py = pos[2*q+1];
    float sp = __fadd_rn(__fmul_rn(px, px), __fmul_rn(py, py));

    float key[16]; int id[16];
#pragma unroll
    for (int i = 0; i < 16; i++) { key[i] = f_inf(); id[i] = 0x7fffffff; }

    int cx = cell_of(px), cy = cell_of(py);

    for (int R = 0;; R++) {
        int xlo = cx - R, xhi = cx + R, ylo = cy - R, yhi = cy + R;
        int xl = max(xlo, 0), xh = min(xhi, GG-1);
        int yl = max(ylo, 0), yh = min(yhi, GG-1);
        for (int yy = yl; yy <= yh; yy++) {
            if (yy == ylo || yy == yhi) {
                int s = g_cellStart[yy*GG + xl];
                int e = g_cellStart[yy*GG + xh + 1];
                SCAN_RANGE(s, e)
            } else {
                if (xlo >= 0) {
                    int s = g_cellStart[yy*GG + xlo];
                    int e = g_cellStart[yy*GG + xlo + 1];
                    SCAN_RANGE(s, e)
                }
                if (xhi <= GG-1) {
                    int s = g_cellStart[yy*GG + xhi];
                    int e = g_cellStart[yy*GG + xhi + 1];
                    SCAN_RANGE(s, e)
                }
            }
        }
        bool full = (xlo <= 0 && ylo <= 0 && xhi >= GG-1 && yhi >= GG-1);
        float x0 = GMINF + xlo * HCELL, x1 = GMINF + (xhi + 1) * HCELL;
        float y0 = GMINF + ylo * HCELL, y1 = GMINF + (yhi + 1) * HCELL;
        float db = fminf(fminf(px - x0, x1 - px), fminf(py - y0, y1 - py));
        if (full || (db > 0.0f && db*db > key[15] + MARGIN)) break;
    }

    float* o = outKnn + (size_t)q * 66;
    __nv_bfloat16* xh = g_AH + (size_t)q * 128;
    __nv_bfloat16* xl = g_AL + (size_t)q * 128;
    float feat[66];
    feat[0] = px; feat[1] = py;
#pragma unroll
    for (int n = 0; n < 16; n++) {
        int mi = id[n];
        feat[2+4*n] = mc[2*mi];
        feat[3+4*n] = mc[2*mi+1];
        feat[4+4*n] = mv[2*mi];
        feat[5+4*n] = mv[2*mi+1];
    }
#pragma unroll
    for (int c = 0; c < 66; c++) {
        o[c] = feat[c];
        __nv_bfloat16 h, l;
        bsplit(feat[c], h, l);
        xh[c] = h; xl[c] = l;
    }
#pragma unroll
    for (int c = 66; c < 128; c++) { xh[c] = __float2bfloat16(0.0f); xl[c] = __float2bfloat16(0.0f); }
}

// ---------------- HMMA bf16x3 GEMM on pre-split planes (LDG fill, 2 CTA/SM) ---
template<int BNT>
__global__ void __launch_bounds__(256, 2)
gemm2_kernel(const __nv_bfloat16* __restrict__ AH, const __nv_bfloat16* __restrict__ AL, int lda,
             const __nv_bfloat16* __restrict__ WH, const __nv_bfloat16* __restrict__ WL,
             const float* __restrict__ bias, float* __restrict__ C,
             int K, int N)
{
    extern __shared__ char sm[];
    constexpr int NW  = BNT / 2;
    constexpr int NB8 = NW / 8;
    constexpr int NG  = NW / 16;
    constexpr int SS  = BNT + 4;
    constexpr int SM_BIAS = 0;
    constexpr int TIL = 2560;
    constexpr int AHI = TIL;
    constexpr int ALO = AHI + 128*144;
    constexpr int BHI = ALO + 128*144;
    constexpr int BLO = BHI + BNT*144;
    constexpr int TEND = BLO + BNT*144;
    constexpr int STGO = TIL;                // aliases tiles in epilogue
    constexpr int RED  = TEND;

    uint32_t sbase = smem_u32(sm);
    int tid = threadIdx.x;
    int wid = tid >> 5, lane = tid & 31;
    int wm = wid & 3, wn = wid >> 2;
    int row0 = blockIdx.y * 128;
    int col0 = blockIdx.x * BNT;

    float* sBias = (float*)(sm + SM_BIAS);
    for (int i = tid; i < BNT; i += 256) sBias[i] = bias[col0 + i];
    __syncthreads();

    float d[2][NB8][4];
#pragma unroll
    for (int mt = 0; mt < 2; mt++)
#pragma unroll
        for (int nb = 0; nb < NB8; nb++)
#pragma unroll
            for (int j = 0; j < 4; j++) d[mt][nb][j] = 0.0f;

    const int nst = K / 64;
    for (int s = 0; s < nst; s++) {
        int k0 = s * 64;
#pragma unroll
        for (int it = 0; it < 8; it++) {
            int idx = tid + it * 256;
            int m = idx >> 4;
            int kc = (idx & 15) * 4;
            size_t go = (size_t)(row0 + m) * lda + k0 + kc;
            *(uint2*)(sm + AHI + m*144 + kc*2) = *(const uint2*)(AH + go);
            *(uint2*)(sm + ALO + m*144 + kc*2) = *(const uint2*)(AL + go);
        }
#pragma unroll
        for (int it = 0; it < BNT/16; it++) {
            int idx = tid + it * 256;
            int n = idx >> 4;
            int kc = (idx & 15) * 4;
            size_t go = (size_t)(col0 + n) * K + k0 + kc;
            *(uint2*)(sm + BHI + n*144 + kc*2) = *(const uint2*)(WH + go);
            *(uint2*)(sm + BLO + n*144 + kc*2) = *(const uint2*)(WL + go);
        }
        __syncthreads();

        int lr = lane & 15, lc = lane >> 4;
#pragma unroll
        for (int kst = 0; kst < 4; kst++) {
            uint32_t koff = (uint32_t)(kst * 16 + lc * 8) * 2;
            uint32_t bh[NG][4], bl[NG][4];
#pragma unroll
            for (int g = 0; g < NG; g++) {
                uint32_t bo = (uint32_t)((wn*NW + g*16 + lr) * 72) * 2 + koff;
                ldsm4(bh[g], sbase + BHI + bo);
                ldsm4(bl[g], sbase + BLO + bo);
            }
#pragma unroll
            for (int mt = 0; mt < 2; mt++) {
                uint32_t ao = (uint32_t)((wm*32 + mt*16 + lr) * 72) * 2 + koff;
                uint32_t ah[4], al[4];
                ldsm4(ah, sbase + AHI + ao);
                ldsm4(al, sbase + ALO + ao);
#pragma unroll
                for (int g = 0; g < NG; g++) {
                    mma16816(d[mt][2*g],   ah, bh[g][0], bh[g][2]);
                    mma16816(d[mt][2*g],   ah, bl[g][0], bl[g][2]);
                    mma16816(d[mt][2*g],   al, bh[g][0], bh[g][2]);
                    mma16816(d[mt][2*g+1], ah, bh[g][1], bh[g][3]);
                    mma16816(d[mt][2*g+1], ah, bl[g][1], bl[g][3]);
                    mma16816(d[mt][2*g+1], al, bh[g][1], bh[g][3]);
                }
            }
        }
        __syncthreads();
    }

    float* stg = (float*)(sm + STGO);
    float* red = (float*)(sm + RED);
#pragma unroll
    for (int mt = 0; mt < 2; mt++)
#pragma unroll
        for (int nb = 0; nb < NB8; nb++) {
            int col = wn*NW + nb*8 + 2*(lane & 3);
            int row = wm*32 + mt*16 + (lane >> 2);
            float b0 = sBias[col], b1 = sBias[col+1];
            stg[row*SS + col]       = d[mt][nb][0] + b0;
            stg[row*SS + col + 1]   = d[mt][nb][1] + b1;
            stg[(row+8)*SS + col]   = d[mt][nb][2] + b0;
            stg[(row+8)*SS + col+1] = d[mt][nb][3] + b1;
        }
    __syncthreads();

    for (int idx = tid; idx < 128 * (BNT/4); idx += 256) {
        int m  = idx / (BNT/4);
        int j4 = (idx % (BNT/4)) * 4;
        float4 v;
        v.x = stg[m*SS + j4 + 0];
        v.y = stg[m*SS + j4 + 1];
        v.z = stg[m*SS + j4 + 2];
        v.w = stg[m*SS + j4 + 3];
        *(float4*)(C + (size_t)(row0 + m) * N + col0 + j4) = v;
    }

#pragma unroll
    for (int c = 0; c < BNT/32; c++) {
        int j = tid & 31, seg = tid >> 5;
        float s2 = 0.0f, q2 = 0.0f;
        for (int r2 = 0; r2 < 16; r2++) {
            float v = stg[(seg*16 + r2) * SS + c*32 + j];
            s2 += v;
            q2 = fmaf(v, v, q2);
        }
        red[seg*32 + j] = s2;
        red[256 + seg*32 + j] = q2;
        __syncthreads();
        if (tid < 32) {
            float s = 0.0f, q = 0.0f;
            for (int u = 0; u < 8; u++) { s += red[u*32 + tid]; q += red[256 + u*32 + tid]; }
            g_psum[blockIdx.y * N + col0 + c*32 + tid] = s;
            g_psq [blockIdx.y * N + col0 + c*32 + tid] = q;
        }
        __syncthreads();
    }
}

// ---------------- BN finalize ----------------
__global__ void bnfin_kernel(const float* __restrict__ g, const float* __restrict__ be, int N) {
    int c = blockIdx.x * 64 + threadIdx.x;
    if (c >= N) return;
    double s = 0.0, q = 0.0;
    for (int rb = 0; rb < 256; rb++) { s += (double)g_psum[rb * N + c]; q += (double)g_psq[rb * N + c]; }
    double mean = s / (double)BB;
    double var  = q / (double)BB - mean * mean;
    float sc = g[c] * rsqrtf((float)var + 1e-5f);
    g_scale[c] = sc;
    g_shift[c] = be[c] - (float)mean * sc;
}

// ---------------- final layer 64 -> 2 (with fused BN5+ReLU) ----------------
__global__ void __launch_bounds__(256) layer6_kernel(
    const float* __restrict__ w6, const float* __restrict__ b6, float* __restrict__ out)
{
    __shared__ float w[128];
    __shared__ float sc[64], sh[64];
    __shared__ float bb2[2];
    int t = threadIdx.x;
    if (t < 128) w[t] = w6[t];
    if (t < 64) { sc[t] = g_scale[t]; sh[t] = g_shift[t]; }
    if (t < 2) bb2[t] = b6[t];
    __syncthreads();
    int r = blockIdx.x * blockDim.x + t;
    if (r >= BB) return;
    const float* x = g_X5 + (size_t)r * 64;
    float a0 = bb2[0], a1 = bb2[1];
#pragma unroll
    for (int k = 0; k < 64; k++) {
        float v = fmaxf(0.0f, fmaf(x[k], sc[k], sh[k]));
        a0 = fmaf(v, w[2*k],   a0);
        a1 = fmaf(v, w[2*k+1], a1);
    }
    out[2*r]   = a0;
    out[2*r+1] = a1;
}

// ---------------- launch ----------------
extern "C" void kernel_launch(void* const* d_in, const int* in_sizes, int n_in,
                              void* d_out, int out_size) {
    const float* pos = (const float*)d_in[0];
    const float* mc  = (const float*)d_in[1];
    const float* mv  = (const float*)d_in[2];
    const float* w1 = (const float*)d_in[3];  const float* b1 = (const float*)d_in[4];
    const float* w2 = (const float*)d_in[5];  const float* b2 = (const float*)d_in[6];
    const float* w3 = (const float*)d_in[7];  const float* b3 = (const float*)d_in[8];
    const float* w4 = (const float*)d_in[9];  const float* b4 = (const float*)d_in[10];
    const float* w5 = (const float*)d_in[11]; const float* b5 = (const float*)d_in[12];
    const float* w6 = (const float*)d_in[13]; const float* b6 = (const float*)d_in[14];
    const float* g1 = (const float*)d_in[15]; const float* be1 = (const float*)d_in[16];
    const float* g2 = (const float*)d_in[17]; const float* be2 = (const float*)d_in[18];
    const float* g3 = (const float*)d_in[19]; const float* be3 = (const float*)d_in[20];
    const float* g4 = (const float*)d_in[21]; const float* be4 = (const float*)d_in[22];
    const float* g5 = (const float*)d_in[23]; const float* be5 = (const float*)d_in[24];
    float* out = (float*)d_out;

    float *X1, *X2, *X3, *X4, *X5;
    cudaGetSymbolAddress((void**)&X1,  g_X1);
    cudaGetSymbolAddress((void**)&X2,  g_X2);
    cudaGetSymbolAddress((void**)&X3,  g_X3);
    cudaGetSymbolAddress((void**)&X4,  g_X4);
    cudaGetSymbolAddress((void**)&X5,  g_X5);
    __nv_bfloat16 *AH, *AL, *W1H, *W1L, *W2H, *W2L, *W3H, *W3L, *W4H, *W4L, *W5H, *W5L;
    cudaGetSymbolAddress((void**)&AH,  g_AH);
    cudaGetSymbolAddress((void**)&AL,  g_AL);
    cudaGetSymbolAddress((void**)&W1H, g_W1H); cudaGetSymbolAddress((void**)&W1L, g_W1L);
    cudaGetSymbolAddress((void**)&W2H, g_W2H); cudaGetSymbolAddress((void**)&W2L, g_W2L);
    cudaGetSymbolAddress((void**)&W3H, g_W3H); cudaGetSymbolAddress((void**)&W3L, g_W3L);
    cudaGetSymbolAddress((void**)&W4H, g_W4H); cudaGetSymbolAddress((void**)&W4L, g_W4L);
    cudaGetSymbolAddress((void**)&W5H, g_W5H); cudaGetSymbolAddress((void**)&W5L, g_W5L);

    const int SMEM128 = 2560 + 2*128*144 + 2*128*144 + 2048;  // 78336
    const int SMEM64  = 2560 + 2*128*144 + 2*64*144  + 2048;  // 59904
    cudaFuncSetAttribute(gemm2_kernel<128>,
                         cudaFuncAttributeMaxDynamicSharedMemorySize, SMEM128);
    cudaFuncSetAttribute(gemm2_kernel<64>,
                         cudaFuncAttributeMaxDynamicSharedMemorySize, SMEM64);

    // grid build + query sort (merged setup: 5 kernels)
    zero_cells_kernel<<<(NCELL + 255) / 256, 256>>>();
    count2_kernel<<<(MM + BB + 255) / 256, 256>>>(mc, pos);
    scan2_kernel<<<2, 256>>>();
    scatter2_kernel<<<(MM + BB + 255) / 256, 256>>>(mc, pos);
    wtconv_all_kernel<<<(253952 + 255) / 256, 256>>>(w1, w2, w3, w4, w5);

    knn_kernel<<<BB / 256, 256>>>(pos, mc, mv, out + (size_t)BB * 2);

    // L1
    gemm2_kernel<128><<<dim3(1, BB/128), 256, SMEM128>>>(AH, AL, 128, W1H, W1L, b1, X1, 128, 128);
    bnfin_kernel<<<2, 64>>>(g1, be1, 128);
    convbn_kernel<<<(BB*128/4 + 255)/256, 256>>>(X1, AH, AL, 128);

    // L2
    gemm2_kernel<128><<<dim3(2, BB/128), 256, SMEM128>>>(AH, AL, 128, W2H, W2L, b2, X2, 128, 256);
    bnfin_kernel<<<4, 64>>>(g2, be2, 256);
    convbn_kernel<<<(BB*256/4 + 255)/256, 256>>>(X2, AH, AL, 256);

    // L3
    gemm2_kernel<128><<<dim3(4, BB/128), 256, SMEM128>>>(AH, AL, 256, W3H, W3L, b3, X3, 256, 512);
    bnfin_kernel<<<8, 64>>>(g3, be3, 512);
    convbn_kernel<<<(BB*512/4 + 255)/256, 256>>>(X3, AH, AL, 512);

    // L4
    gemm2_kernel<128><<<dim3(1, BB/128), 256, SMEM128>>>(AH, AL, 512, W4H, W4L, b4, X4, 512, 128);
    bnfin_kernel<<<2, 64>>>(g4, be4, 128);
    convbn_kernel<<<(BB*128/4 + 255)/256, 256>>>(X4, AH, AL, 128);

    // L5
    gemm2_kernel<64><<<dim3(1, BB/128), 256, SMEM64>>>(AH, AL, 128, W5H, W5L, b5, X5, 128, 64);
    bnfin_kernel<<<1, 64>>>(g5, be5, 64);

    // L6
    layer6_kernel<<<BB / 256, 256>>>(w6, b6, out);
}